// round 1
// baseline (speedup 1.0000x reference)
#include <cuda_runtime.h>

// Conv4d: x(2,8,16,40,40,40) * W(3,32,8,3,3,3) + bias(3,32) -> out(2,32,16,40,40,40)
// out[b,co,t,d,h,w] = sum_{kt,ci,kd,kh,kw} x[b,ci,t+kt-1,d+kd-1,h+kh-1,w+kw-1]*W[kt,co,ci,kd,kh,kw]
//                     + sum_{kt valid} bias[kt,co]
//
// Block: (b,t) fixed, co-group of 8, spatial tile 4(d) x 4(h) x 40(w).
// Thread: 8 co x 4 w register tile (32 accumulators).
// smem: x slab 4ci x 6 x 6 x 42 (6048 f) + weights 8co x 4ci x 27 (864 f) = 27.6 KB static.

#define NTHREADS 160

__global__ void __launch_bounds__(NTHREADS) conv4d_kernel(
    const float* __restrict__ x, const float* __restrict__ weight,
    const float* __restrict__ bias, float* __restrict__ out)
{
    __shared__ float sx[4 * 6 * 6 * 42];   // [ci_local][dd][hh][ww] 6048 floats
    __shared__ float sw[8 * 4 * 27];       // [co][ci_local*27 + r]   864 floats

    const int tid = threadIdx.x;
    const int wg  = tid % 10;          // w group: w0 = wg*4
    const int hl  = (tid / 10) % 4;    // 0..3
    const int dl  = tid / 40;          // 0..3
    const int wg4 = wg * 4;

    const int bx  = blockIdx.x;        // 0..99 -> (d0,h0)
    const int cog = blockIdx.y;        // 0..3  -> co base = cog*8
    const int bz  = blockIdx.z;        // 0..31 -> (b,t)
    const int d0  = (bx % 10) * 4;
    const int h0  = (bx / 10) * 4;
    const int b   = bz >> 4;
    const int t   = bz & 15;

    float acc[8][4];
    // init accumulators with effective bias (only temporally-valid kt contribute)
    #pragma unroll
    for (int co = 0; co < 8; ++co) {
        float s = 0.f;
        #pragma unroll
        for (int kt = 0; kt < 3; ++kt) {
            int tf = t + kt - 1;
            if (tf >= 0 && tf < 16) s += bias[kt * 32 + cog * 8 + co];
        }
        #pragma unroll
        for (int i = 0; i < 4; ++i) acc[co][i] = s;
    }

    for (int kt = 0; kt < 3; ++kt) {
        const int tf = t + kt - 1;
        if (tf < 0 || tf >= 16) continue;           // uniform across block
        const float* xg = x + b * 8192000 + tf * 64000;   // + ci*1024000 later

        for (int cib = 0; cib < 2; ++cib) {         // ci halves: [0,4) and [4,8)
            __syncthreads();
            // --- stage x slab: 4 ci x 6 x 6 x 42 (halo of 1, zero padded) ---
            for (int idx = tid; idx < 4 * 1512; idx += NTHREADS) {
                int ci = idx / 1512;
                int r  = idx - ci * 1512;
                int dd = r / 252;
                int r2 = r - dd * 252;
                int hh = r2 / 42;
                int ww = r2 - hh * 42;
                int gd = d0 + dd - 1, gh = h0 + hh - 1, gw = ww - 1;
                float v = 0.f;
                if ((unsigned)gd < 40u && (unsigned)gh < 40u && (unsigned)gw < 40u)
                    v = xg[(cib * 4 + ci) * 1024000 + gd * 1600 + gh * 40 + gw];
                sx[idx] = v;
            }
            // --- stage weights: 8 co x (4 ci x 27), contiguous per co ---
            for (int idx = tid; idx < 8 * 108; idx += NTHREADS) {
                int co = idx / 108;
                int r  = idx - co * 108;
                sw[idx] = weight[(kt * 32 + cog * 8 + co) * 216 + cib * 108 + r];
            }
            __syncthreads();

            #pragma unroll 1
            for (int ci = 0; ci < 4; ++ci) {
                #pragma unroll 1
                for (int kd = 0; kd < 3; ++kd) {
                    const float* xb = &sx[((ci * 6 + dl + kd) * 6 + hl) * 42 + wg4];
                    const float* wb = &sw[ci * 27 + kd * 9];
                    #pragma unroll
                    for (int kh = 0; kh < 3; ++kh) {
                        const float* xr = xb + kh * 42;
                        float x0 = xr[0], x1 = xr[1], x2 = xr[2];
                        float x3 = xr[3], x4 = xr[4], x5 = xr[5];
                        #pragma unroll
                        for (int co = 0; co < 8; ++co) {
                            const float* wp = wb + co * 108 + kh * 3;
                            float w0 = wp[0], w1 = wp[1], w2 = wp[2];
                            acc[co][0] = fmaf(x0, w0, acc[co][0]);
                            acc[co][1] = fmaf(x1, w0, acc[co][1]);
                            acc[co][2] = fmaf(x2, w0, acc[co][2]);
                            acc[co][3] = fmaf(x3, w0, acc[co][3]);
                            acc[co][0] = fmaf(x1, w1, acc[co][0]);
                            acc[co][1] = fmaf(x2, w1, acc[co][1]);
                            acc[co][2] = fmaf(x3, w1, acc[co][2]);
                            acc[co][3] = fmaf(x4, w1, acc[co][3]);
                            acc[co][0] = fmaf(x2, w2, acc[co][0]);
                            acc[co][1] = fmaf(x3, w2, acc[co][1]);
                            acc[co][2] = fmaf(x4, w2, acc[co][2]);
                            acc[co][3] = fmaf(x5, w2, acc[co][3]);
                        }
                    }
                }
            }
        }
    }

    // --- store: out[b, cog*8+co, t, d0+dl, h0+hl, wg*4 .. +3] as float4 ---
    const int obase = ((b * 32 + cog * 8) * 16 + t) * 64000
                    + (d0 + dl) * 1600 + (h0 + hl) * 40 + wg4;
    #pragma unroll
    for (int co = 0; co < 8; ++co) {
        float4 v = make_float4(acc[co][0], acc[co][1], acc[co][2], acc[co][3]);
        *reinterpret_cast<float4*>(out + obase + co * 1024000) = v;
    }
}

extern "C" void kernel_launch(void* const* d_in, const int* in_sizes, int n_in,
                              void* d_out, int out_size) {
    // identify inputs by size (robust to ordering): x=16384000, weight=20736, bias=96
    const float* x = nullptr; const float* w = nullptr; const float* bias = nullptr;
    for (int i = 0; i < n_in; ++i) {
        if (in_sizes[i] == 16384000)    x    = (const float*)d_in[i];
        else if (in_sizes[i] == 20736)  w    = (const float*)d_in[i];
        else if (in_sizes[i] == 96)     bias = (const float*)d_in[i];
    }
    float* out = (float*)d_out;
    dim3 grid(100, 4, 32);   // (d-tiles * h-tiles, co groups, b*t)
    conv4d_kernel<<<grid, NTHREADS>>>(x, w, bias, out);
}